// round 11
// baseline (speedup 1.0000x reference)
#include <cuda_runtime.h>
#include <cuda_bf16.h>
#include <cstdint>
#include <cstddef>

// ---------------------------------------------------------------------------
// Problem constants
// ---------------------------------------------------------------------------
namespace {
constexpr int B = 8, N = 4096, M = 4096, D = 128;
constexpr int BN = B * N;  // 32768 (== B*M)
constexpr int MBLK = M / 128;  // 32 col-blocks per row
constexpr int NBLK = N / 128;  // 32 row-blocks per col
constexpr float RATIO2 = 0.64f;  // 0.8^2
constexpr float DIST2  = 0.49f;  // 0.7^2

// GEMM smem layout: 4 operand tiles of 128 rows x (128 bf16 + 8 pad) = 272B/row
constexpr int ROWB   = 272;                 // padded row bytes (17 * 16B)
constexpr int TILEB  = 128 * ROWB;          // 34816 B per operand tile
constexpr int SA_H = 0;
constexpr int SA_L = TILEB;
constexpr int SB_H = 2 * TILEB;
constexpr int SB_L = 3 * TILEB;
constexpr int SMEM_BYTES = 4 * TILEB;       // 139264
}  // namespace

// ---------------------------------------------------------------------------
// Device scratch (no allocations allowed)
// ---------------------------------------------------------------------------
__device__ __nv_bfloat16 g_ah[(size_t)B * N * D];
__device__ __nv_bfloat16 g_al[(size_t)B * N * D];
__device__ __nv_bfloat16 g_bh[(size_t)B * M * D];
__device__ __nv_bfloat16 g_bl[(size_t)B * M * D];

struct alignas(16) Top2 { float v1, v2; int i1, i2; };
__device__ Top2 g_rowpart[(size_t)BN * MBLK];  // per (b*N+n, cblk)
__device__ Top2 g_colpart[(size_t)BN * NBLK];  // per (b*M+m, rblk)
__device__ int  g_m0[B * N];
__device__ int  g_m1[B * M];

// ---------------------------------------------------------------------------
// PTX helpers (portable: sm_80+ instructions only, safe at target sm_103)
// ---------------------------------------------------------------------------
__device__ __forceinline__ uint32_t smem_u32(const void* p) {
    uint32_t a;
    asm("{ .reg .u64 t; cvta.to.shared.u64 t, %1; cvt.u32.u64 %0, t; }" : "=r"(a) : "l"(p));
    return a;
}

__device__ __forceinline__ void ldmatrix_x4(uint32_t (&r)[4], uint32_t addr) {
    asm volatile("ldmatrix.sync.aligned.m8n8.x4.shared.b16 {%0,%1,%2,%3}, [%4];"
                 : "=r"(r[0]), "=r"(r[1]), "=r"(r[2]), "=r"(r[3]) : "r"(addr));
}

__device__ __forceinline__ void mma_16816(float (&d)[4], const uint32_t (&a)[4],
                                          const uint32_t* b) {
    asm volatile(
        "mma.sync.aligned.m16n8k16.row.col.f32.bf16.bf16.f32 "
        "{%0,%1,%2,%3}, {%4,%5,%6,%7}, {%8,%9}, {%0,%1,%2,%3};"
        : "+f"(d[0]), "+f"(d[1]), "+f"(d[2]), "+f"(d[3])
        : "r"(a[0]), "r"(a[1]), "r"(a[2]), "r"(a[3]), "r"(b[0]), "r"(b[1]));
}

// ---------------------------------------------------------------------------
// Top-2 helpers (lax.top_k semantics: larger wins; tie -> lower index)
// Order-independent given exact fp32 values, so fused partial reductions are
// bit-identical to a serial scan.
// ---------------------------------------------------------------------------
__device__ __forceinline__ void t2_init(Top2& t) {
    t.v1 = -2e30f; t.v2 = -2e30f; t.i1 = 0x7fffffff; t.i2 = 0x7fffffff;
}
__device__ __forceinline__ void t2_push(Top2& t, float v, int i) {
    if (v > t.v1 || (v == t.v1 && i < t.i1)) {
        t.v2 = t.v1; t.i2 = t.i1; t.v1 = v; t.i1 = i;
    } else if (v > t.v2 || (v == t.v2 && i < t.i2)) {
        t.v2 = v; t.i2 = i;
    }
}
__device__ __forceinline__ void t2_merge(Top2& a, const Top2& b) {
    t2_push(a, b.v1, b.i1);
    t2_push(a, b.v2, b.i2);
}
__device__ __forceinline__ Top2 t2_shfl_xor(const Top2& t, int o) {
    Top2 u;
    u.v1 = __shfl_xor_sync(0xffffffffu, t.v1, o);
    u.v2 = __shfl_xor_sync(0xffffffffu, t.v2, o);
    u.i1 = __shfl_xor_sync(0xffffffffu, t.i1, o);
    u.i2 = __shfl_xor_sync(0xffffffffu, t.i2, o);
    return u;
}
__device__ __forceinline__ int t2_match(const Top2& t) {
    float d0 = 2.0f * (1.0f - t.v1);
    float d1 = 2.0f * (1.0f - t.v2);
    bool ok = (d0 <= RATIO2 * d1) && (d0 <= DIST2);
    return ok ? t.i1 : -1;
}

// ---------------------------------------------------------------------------
// Kernel 1: l2-normalize rows, split fp32 -> bf16 hi + bf16 lo
// ---------------------------------------------------------------------------
__global__ void norm_split_kernel(const float* __restrict__ d0, const float* __restrict__ d1) {
    int row  = blockIdx.x * 8 + (threadIdx.x >> 5);
    int lane = threadIdx.x & 31;

    const float* src;
    __nv_bfloat16 *ph, *pl;
    if (row < B * N) {
        src = d0 + (size_t)row * D;
        ph = g_ah + (size_t)row * D;
        pl = g_al + (size_t)row * D;
    } else {
        int r = row - B * N;
        src = d1 + (size_t)r * D;
        ph = g_bh + (size_t)r * D;
        pl = g_bl + (size_t)r * D;
    }
    float4 x = reinterpret_cast<const float4*>(src)[lane];
    float s = x.x * x.x + x.y * x.y + x.z * x.z + x.w * x.w;
#pragma unroll
    for (int o = 16; o > 0; o >>= 1) s += __shfl_xor_sync(0xffffffffu, s, o);
    float nrm = fmaxf(sqrtf(s), 1e-12f);

    float y[4] = {x.x / nrm, x.y / nrm, x.z / nrm, x.w / nrm};
#pragma unroll
    for (int i = 0; i < 4; ++i) {
        __nv_bfloat16 h = __float2bfloat16(y[i]);
        __nv_bfloat16 l = __float2bfloat16(y[i] - __bfloat162float(h));
        ph[lane * 4 + i] = h;
        pl[lane * 4 + i] = l;
    }
}

// ---------------------------------------------------------------------------
// Kernel 2: bf16 mma.sync GEMM  sim[b, r0:+128, c0:+128] = A @ B^T
//           split-bf16 (AhBh + AhBl + AlBh, fp32 accum), plus FUSED
//           per-row / per-column Top2 partials written alongside sim.
// ---------------------------------------------------------------------------
__global__ void __launch_bounds__(256, 1) sim_gemm_kernel(float* __restrict__ sim) {
    extern __shared__ char sm[];
    const int tid  = threadIdx.x;
    const int wid  = tid >> 5;
    const int lane = tid & 31;
    const int bz    = blockIdx.z;
    const int rbase = blockIdx.y * 128;  // d0 rows
    const int cbase = blockIdx.x * 128;  // d1 rows

    // ---- load all four operand tiles into padded smem (16B chunks) ----
    {
        const uint4* gAh = reinterpret_cast<const uint4*>(g_ah + ((size_t)bz * N + rbase) * D);
        const uint4* gAl = reinterpret_cast<const uint4*>(g_al + ((size_t)bz * N + rbase) * D);
        const uint4* gBh = reinterpret_cast<const uint4*>(g_bh + ((size_t)bz * M + cbase) * D);
        const uint4* gBl = reinterpret_cast<const uint4*>(g_bl + ((size_t)bz * M + cbase) * D);
#pragma unroll
        for (int i = tid; i < 2048; i += 256) {  // 128 rows * 16 chunks
            int r = i >> 4, j = i & 15;
            size_t so = (size_t)r * ROWB + j * 16;
            *reinterpret_cast<uint4*>(sm + SA_H + so) = gAh[i];
            *reinterpret_cast<uint4*>(sm + SA_L + so) = gAl[i];
            *reinterpret_cast<uint4*>(sm + SB_H + so) = gBh[i];
            *reinterpret_cast<uint4*>(sm + SB_L + so) = gBl[i];
        }
    }
    __syncthreads();

    const uint32_t sb = smem_u32(sm);
    const int wm = (wid & 3) * 32;   // warp row offset in tile
    const int wn = (wid >> 2) * 64;  // warp col offset in tile

    const int a_r  = ((lane >> 3) & 1) * 8 + (lane & 7);
    const int a_cb = ((lane >> 4) & 1) * 16;
    const int b_r  = ((lane >> 4) & 1) * 8 + (lane & 7);
    const int b_cb = ((lane >> 3) & 1) * 16;

    float acc[2][8][4];
#pragma unroll
    for (int mt = 0; mt < 2; ++mt)
#pragma unroll
        for (int nt = 0; nt < 8; ++nt)
#pragma unroll
            for (int q = 0; q < 4; ++q) acc[mt][nt][q] = 0.0f;

#pragma unroll
    for (int p = 0; p < 3; ++p) {  // (Ah,Bh), (Ah,Bl), (Al,Bh)
        const uint32_t Ab = sb + (p == 2 ? SA_L : SA_H);
        const uint32_t Bb = sb + (p == 1 ? SB_L : SB_H);
#pragma unroll
        for (int ks = 0; ks < 8; ++ks) {
            uint32_t a[2][4], b[4][4];
#pragma unroll
            for (int mt = 0; mt < 2; ++mt)
                ldmatrix_x4(a[mt], Ab + (uint32_t)(wm + mt * 16 + a_r) * ROWB + a_cb + ks * 32);
#pragma unroll
            for (int nt2 = 0; nt2 < 4; ++nt2)
                ldmatrix_x4(b[nt2], Bb + (uint32_t)(wn + nt2 * 16 + b_r) * ROWB + b_cb + ks * 32);
#pragma unroll
            for (int mt = 0; mt < 2; ++mt)
#pragma unroll
                for (int nt = 0; nt < 8; ++nt)
                    mma_16816(acc[mt][nt], a[mt], &b[nt >> 1][(nt & 1) * 2]);
        }
    }

    // ---- sim stores (global, no smem involved) ----
    const int rr = rbase + wm + (lane >> 2);            // global row of frag row 0
    const int cc = cbase + wn + (lane & 3) * 2;         // global col of frag col 0
#pragma unroll
    for (int mt = 0; mt < 2; ++mt)
#pragma unroll
        for (int nt = 0; nt < 8; ++nt) {
            float* p = sim + ((size_t)bz * N + rr + mt * 16) * M + cc + nt * 8;
            *reinterpret_cast<float2*>(p) = make_float2(acc[mt][nt][0], acc[mt][nt][1]);
            *reinterpret_cast<float2*>(p + 8 * (size_t)M) =
                make_float2(acc[mt][nt][2], acc[mt][nt][3]);
        }

    // ---- fused per-row Top2 over this tile's 128 columns ----
    // thread owns rows rr + {0,8,16,24} (rs = mt*2 + hi), 16 cols each
    Top2 rt[4];
#pragma unroll
    for (int rs = 0; rs < 4; ++rs) t2_init(rt[rs]);
#pragma unroll
    for (int mt = 0; mt < 2; ++mt)
#pragma unroll
        for (int nt = 0; nt < 8; ++nt)
#pragma unroll
            for (int q = 0; q < 4; ++q)
                t2_push(rt[mt * 2 + (q >> 1)], acc[mt][nt][q], cc + nt * 8 + (q & 1));
#pragma unroll
    for (int o = 1; o < 4; o <<= 1)
#pragma unroll
        for (int rs = 0; rs < 4; ++rs) {
            Top2 u = t2_shfl_xor(rt[rs], o);
            t2_merge(rt[rs], u);
        }

    __syncthreads();  // operand smem dead -> reuse as reduction scratch
    Top2* rowsh = reinterpret_cast<Top2*>(sm);           // [2 col-halves][128 rows]
    Top2* colsh = reinterpret_cast<Top2*>(sm + 4096);    // [4 row-groups][128 cols]

    if ((lane & 3) == 0) {
#pragma unroll
        for (int rs = 0; rs < 4; ++rs)
            rowsh[(wid >> 2) * 128 + wm + (lane >> 2) + rs * 8] = rt[rs];
    }

    // ---- fused per-column Top2 over this tile's 128 rows ----
#pragma unroll
    for (int nt = 0; nt < 8; ++nt) {
        Top2 ct0, ct1;
        t2_init(ct0); t2_init(ct1);
#pragma unroll
        for (int mt = 0; mt < 2; ++mt)
#pragma unroll
            for (int hi = 0; hi < 2; ++hi) {
                int rown = rr + mt * 16 + hi * 8;  // global n index
                t2_push(ct0, acc[mt][nt][hi * 2 + 0], rown);
                t2_push(ct1, acc[mt][nt][hi * 2 + 1], rown);
            }
#pragma unroll
        for (int o = 4; o < 32; o <<= 1) {
            Top2 u0 = t2_shfl_xor(ct0, o); t2_merge(ct0, u0);
            Top2 u1 = t2_shfl_xor(ct1, o); t2_merge(ct1, u1);
        }
        if ((lane >> 2) == 0) {
            int cl = wn + (lane & 3) * 2 + nt * 8;  // local col 0..127
            colsh[(wid & 3) * 128 + cl]     = ct0;
            colsh[(wid & 3) * 128 + cl + 1] = ct1;
        }
    }
    __syncthreads();

    if (tid < 128) {
        Top2 r = rowsh[tid];
        t2_merge(r, rowsh[128 + tid]);
        g_rowpart[((size_t)(bz * N + rbase + tid)) * MBLK + blockIdx.x] = r;

        Top2 c = colsh[tid];
        t2_merge(c, colsh[128 + tid]);
        t2_merge(c, colsh[256 + tid]);
        t2_merge(c, colsh[384 + tid]);
        g_colpart[((size_t)(bz * M + cbase + tid)) * NBLK + blockIdx.y] = c;
    }
}

// ---------------------------------------------------------------------------
// Kernel 3/4: merge the 32 per-block partials (one warp per row/col)
// ---------------------------------------------------------------------------
__global__ void row_merge_kernel() {
    int row  = blockIdx.x * 8 + (threadIdx.x >> 5);  // b*N + n
    int lane = threadIdx.x & 31;
    Top2 t = g_rowpart[(size_t)row * MBLK + lane];
#pragma unroll
    for (int o = 16; o > 0; o >>= 1) {
        Top2 u = t2_shfl_xor(t, o);
        t2_merge(t, u);
    }
    if (lane == 0) g_m0[row] = t2_match(t);
}

__global__ void col_merge_kernel() {
    int col  = blockIdx.x * 8 + (threadIdx.x >> 5);  // b*M + m
    int lane = threadIdx.x & 31;
    Top2 t = g_colpart[(size_t)col * NBLK + lane];
#pragma unroll
    for (int o = 16; o > 0; o >>= 1) {
        Top2 u = t2_shfl_xor(t, o);
        t2_merge(t, u);
    }
    if (lane == 0) g_m1[col] = t2_match(t);
}

// ---------------------------------------------------------------------------
// Kernel 5: mutual check + write matches/mscores
//   out layout: [matches0 | matches1 | mscores0 | mscores1 | sim]
// ---------------------------------------------------------------------------
__global__ void finalize_kernel(float* __restrict__ out) {
    int idx = blockIdx.x * 256 + threadIdx.x;  // b*N + n  (N == M)
    int b = idx / N, n = idx % N;

    int m0v = g_m0[idx];
    bool ok0 = (m0v > -1) && (g_m1[b * M + m0v] == n);
    out[idx]          = ok0 ? (float)m0v : -1.0f;
    out[2 * BN + idx] = ok0 ? 1.0f : 0.0f;

    int m1v = g_m1[idx];
    bool ok1 = (m1v > -1) && (g_m0[b * N + m1v] == n);
    out[BN + idx]     = ok1 ? (float)m1v : -1.0f;
    out[3 * BN + idx] = ok1 ? 1.0f : 0.0f;
}

// ---------------------------------------------------------------------------
// Launch
// ---------------------------------------------------------------------------
extern "C" void kernel_launch(void* const* d_in, const int* in_sizes, int n_in,
                              void* d_out, int out_size) {
    (void)in_sizes; (void)n_in; (void)out_size;
    const float* d0 = (const float*)d_in[0];
    const float* d1 = (const float*)d_in[1];
    float* out = (float*)d_out;
    float* sim = out + 4 * (size_t)BN;

    cudaFuncSetAttribute(sim_gemm_kernel,
                         cudaFuncAttributeMaxDynamicSharedMemorySize, SMEM_BYTES);

    norm_split_kernel<<<(B * N + B * M) / 8, 256>>>(d0, d1);
    sim_gemm_kernel<<<dim3(M / 128, N / 128, B), 256, SMEM_BYTES>>>(sim);
    row_merge_kernel<<<BN / 8, 256>>>();
    col_merge_kernel<<<BN / 8, 256>>>();
    finalize_kernel<<<BN / 256, 256>>>(out);
}

// round 12
// speedup vs baseline: 2.0456x; 2.0456x over previous
#include <cuda_runtime.h>
#include <cuda_bf16.h>
#include <cstdint>
#include <cstddef>

// ---------------------------------------------------------------------------
// Problem constants
// ---------------------------------------------------------------------------
namespace {
constexpr int B = 8, N = 4096, M = 4096, D = 128;
constexpr int BN = B * N;  // 32768 (== B*M)
constexpr int NSPLIT = 8;  // row-splits for the column pass
constexpr float RATIO2 = 0.64f;  // 0.8^2
constexpr float DIST2  = 0.49f;  // 0.7^2

// GEMM smem layout: 4 operand tiles of 128 rows x (128 bf16 + 8 pad) = 272B/row
constexpr int ROWB   = 272;                 // padded row bytes (17 * 16B)
constexpr int TILEB  = 128 * ROWB;          // 34816 B per operand tile
constexpr int SA_H = 0;
constexpr int SA_L = TILEB;
constexpr int SB_H = 2 * TILEB;
constexpr int SB_L = 3 * TILEB;
constexpr int SMEM_BYTES = 4 * TILEB;       // 139264
}  // namespace

// ---------------------------------------------------------------------------
// Device scratch (no allocations allowed)
// ---------------------------------------------------------------------------
__device__ __nv_bfloat16 g_ah[(size_t)B * N * D];
__device__ __nv_bfloat16 g_al[(size_t)B * N * D];
__device__ __nv_bfloat16 g_bh[(size_t)B * M * D];
__device__ __nv_bfloat16 g_bl[(size_t)B * M * D];

struct alignas(16) Top2 { float v1, v2; int i1, i2; };
__device__ Top2 g_colpart[(size_t)B * M * NSPLIT];  // [(b*M+m)][nsplit]
__device__ int  g_m0[B * N];
__device__ int  g_m1[B * M];

// ---------------------------------------------------------------------------
// PTX helpers (portable: sm_80+ instructions only, safe at target sm_103)
// ---------------------------------------------------------------------------
__device__ __forceinline__ uint32_t smem_u32(const void* p) {
    uint32_t a;
    asm("{ .reg .u64 t; cvta.to.shared.u64 t, %1; cvt.u32.u64 %0, t; }" : "=r"(a) : "l"(p));
    return a;
}

__device__ __forceinline__ void ldmatrix_x4(uint32_t (&r)[4], uint32_t addr) {
    asm volatile("ldmatrix.sync.aligned.m8n8.x4.shared.b16 {%0,%1,%2,%3}, [%4];"
                 : "=r"(r[0]), "=r"(r[1]), "=r"(r[2]), "=r"(r[3]) : "r"(addr));
}

__device__ __forceinline__ void mma_16816(float (&d)[4], const uint32_t (&a)[4],
                                          const uint32_t* b) {
    asm volatile(
        "mma.sync.aligned.m16n8k16.row.col.f32.bf16.bf16.f32 "
        "{%0,%1,%2,%3}, {%4,%5,%6,%7}, {%8,%9}, {%0,%1,%2,%3};"
        : "+f"(d[0]), "+f"(d[1]), "+f"(d[2]), "+f"(d[3])
        : "r"(a[0]), "r"(a[1]), "r"(a[2]), "r"(a[3]), "r"(b[0]), "r"(b[1]));
}

// ---------------------------------------------------------------------------
// Top-2 helpers (lax.top_k semantics: larger wins; tie -> lower index)
// Order-independent on exact fp32 values, so partial merges are exact.
// ---------------------------------------------------------------------------
__device__ __forceinline__ void t2_init(Top2& t) {
    t.v1 = -2e30f; t.v2 = -2e30f; t.i1 = 0x7fffffff; t.i2 = 0x7fffffff;
}
__device__ __forceinline__ void t2_push(Top2& t, float v, int i) {
    if (v > t.v1 || (v == t.v1 && i < t.i1)) {
        t.v2 = t.v1; t.i2 = t.i1; t.v1 = v; t.i1 = i;
    } else if (v > t.v2 || (v == t.v2 && i < t.i2)) {
        t.v2 = v; t.i2 = i;
    }
}
__device__ __forceinline__ void t2_merge(Top2& a, const Top2& b) {
    t2_push(a, b.v1, b.i1);
    t2_push(a, b.v2, b.i2);
}
__device__ __forceinline__ Top2 t2_shfl_xor(const Top2& t, int o) {
    Top2 u;
    u.v1 = __shfl_xor_sync(0xffffffffu, t.v1, o);
    u.v2 = __shfl_xor_sync(0xffffffffu, t.v2, o);
    u.i1 = __shfl_xor_sync(0xffffffffu, t.i1, o);
    u.i2 = __shfl_xor_sync(0xffffffffu, t.i2, o);
    return u;
}
__device__ __forceinline__ int t2_match(const Top2& t) {
    float d0 = 2.0f * (1.0f - t.v1);
    float d1 = 2.0f * (1.0f - t.v2);
    bool ok = (d0 <= RATIO2 * d1) && (d0 <= DIST2);
    return ok ? t.i1 : -1;
}

// ---------------------------------------------------------------------------
// Kernel 1: l2-normalize rows, split fp32 -> bf16 hi + bf16 lo
// ---------------------------------------------------------------------------
__global__ void norm_split_kernel(const float* __restrict__ d0, const float* __restrict__ d1) {
    int row  = blockIdx.x * 8 + (threadIdx.x >> 5);
    int lane = threadIdx.x & 31;

    const float* src;
    __nv_bfloat16 *ph, *pl;
    if (row < B * N) {
        src = d0 + (size_t)row * D;
        ph = g_ah + (size_t)row * D;
        pl = g_al + (size_t)row * D;
    } else {
        int r = row - B * N;
        src = d1 + (size_t)r * D;
        ph = g_bh + (size_t)r * D;
        pl = g_bl + (size_t)r * D;
    }
    float4 x = reinterpret_cast<const float4*>(src)[lane];
    float s = x.x * x.x + x.y * x.y + x.z * x.z + x.w * x.w;
#pragma unroll
    for (int o = 16; o > 0; o >>= 1) s += __shfl_xor_sync(0xffffffffu, s, o);
    float nrm = fmaxf(sqrtf(s), 1e-12f);

    float y[4] = {x.x / nrm, x.y / nrm, x.z / nrm, x.w / nrm};
#pragma unroll
    for (int i = 0; i < 4; ++i) {
        __nv_bfloat16 h = __float2bfloat16(y[i]);
        __nv_bfloat16 l = __float2bfloat16(y[i] - __bfloat162float(h));
        ph[lane * 4 + i] = h;
        pl[lane * 4 + i] = l;
    }
}

// ---------------------------------------------------------------------------
// Kernel 2: bf16 mma.sync GEMM  sim[b, r0:+128, c0:+128] = A @ B^T
//           split-bf16 (AhBh + AhBl + AlBh, fp32 accum). Clean epilogue
//           (direct float2 stores only) — keeps registers for the mainloop.
// ---------------------------------------------------------------------------
__global__ void __launch_bounds__(256, 1) sim_gemm_kernel(float* __restrict__ sim) {
    extern __shared__ char sm[];
    const int tid  = threadIdx.x;
    const int wid  = tid >> 5;
    const int lane = tid & 31;
    const int bz    = blockIdx.z;
    const int rbase = blockIdx.y * 128;  // d0 rows
    const int cbase = blockIdx.x * 128;  // d1 rows

    // ---- load all four operand tiles into padded smem (16B chunks) ----
    {
        const uint4* gAh = reinterpret_cast<const uint4*>(g_ah + ((size_t)bz * N + rbase) * D);
        const uint4* gAl = reinterpret_cast<const uint4*>(g_al + ((size_t)bz * N + rbase) * D);
        const uint4* gBh = reinterpret_cast<const uint4*>(g_bh + ((size_t)bz * M + cbase) * D);
        const uint4* gBl = reinterpret_cast<const uint4*>(g_bl + ((size_t)bz * M + cbase) * D);
#pragma unroll
        for (int i = tid; i < 2048; i += 256) {  // 128 rows * 16 chunks
            int r = i >> 4, j = i & 15;
            size_t so = (size_t)r * ROWB + j * 16;
            *reinterpret_cast<uint4*>(sm + SA_H + so) = gAh[i];
            *reinterpret_cast<uint4*>(sm + SA_L + so) = gAl[i];
            *reinterpret_cast<uint4*>(sm + SB_H + so) = gBh[i];
            *reinterpret_cast<uint4*>(sm + SB_L + so) = gBl[i];
        }
    }
    __syncthreads();

    const uint32_t sb = smem_u32(sm);
    const int wm = (wid & 3) * 32;   // warp row offset in tile
    const int wn = (wid >> 2) * 64;  // warp col offset in tile

    const int a_r  = ((lane >> 3) & 1) * 8 + (lane & 7);
    const int a_cb = ((lane >> 4) & 1) * 16;
    const int b_r  = ((lane >> 4) & 1) * 8 + (lane & 7);
    const int b_cb = ((lane >> 3) & 1) * 16;

    float acc[2][8][4];
#pragma unroll
    for (int mt = 0; mt < 2; ++mt)
#pragma unroll
        for (int nt = 0; nt < 8; ++nt)
#pragma unroll
            for (int q = 0; q < 4; ++q) acc[mt][nt][q] = 0.0f;

#pragma unroll
    for (int p = 0; p < 3; ++p) {  // (Ah,Bh), (Ah,Bl), (Al,Bh)
        const uint32_t Ab = sb + (p == 2 ? SA_L : SA_H);
        const uint32_t Bb = sb + (p == 1 ? SB_L : SB_H);
#pragma unroll
        for (int ks = 0; ks < 8; ++ks) {
            uint32_t a[2][4], b[4][4];
#pragma unroll
            for (int mt = 0; mt < 2; ++mt)
                ldmatrix_x4(a[mt], Ab + (uint32_t)(wm + mt * 16 + a_r) * ROWB + a_cb + ks * 32);
#pragma unroll
            for (int nt2 = 0; nt2 < 4; ++nt2)
                ldmatrix_x4(b[nt2], Bb + (uint32_t)(wn + nt2 * 16 + b_r) * ROWB + b_cb + ks * 32);
#pragma unroll
            for (int mt = 0; mt < 2; ++mt)
#pragma unroll
                for (int nt = 0; nt < 8; ++nt)
                    mma_16816(acc[mt][nt], a[mt], &b[nt >> 1][(nt & 1) * 2]);
        }
    }

    // ---- epilogue: direct float2 stores ----
    const int rr = rbase + wm + (lane >> 2);
    const int cc = cbase + wn + (lane & 3) * 2;
#pragma unroll
    for (int mt = 0; mt < 2; ++mt)
#pragma unroll
        for (int nt = 0; nt < 8; ++nt) {
            float* p = sim + ((size_t)bz * N + rr + mt * 16) * M + cc + nt * 8;
            *reinterpret_cast<float2*>(p) = make_float2(acc[mt][nt][0], acc[mt][nt][1]);
            *reinterpret_cast<float2*>(p + 8 * (size_t)M) =
                make_float2(acc[mt][nt][2], acc[mt][nt][3]);
        }
}

// ---------------------------------------------------------------------------
// Kernel 3: per-row top-2 over M. One WARP per row, float4 loads,
//           two independent push chains for ILP, shfl-xor merge.
// ---------------------------------------------------------------------------
__global__ void row_top2_kernel(const float* __restrict__ sim) {
    int row  = blockIdx.x * 8 + (threadIdx.x >> 5);  // b*N + n
    int lane = threadIdx.x & 31;
    const float4* p = reinterpret_cast<const float4*>(sim + (size_t)row * M);

    Top2 t0, t1;
    t2_init(t0); t2_init(t1);
#pragma unroll
    for (int it = 0; it < 16; ++it) {  // 32 float4 per lane total
        int j0 = lane + (2 * it) * 32;
        int j1 = lane + (2 * it + 1) * 32;
        float4 x = p[j0];
        float4 y = p[j1];
        int cx = j0 * 4, cy = j1 * 4;
        t2_push(t0, x.x, cx);     t2_push(t0, x.y, cx + 1);
        t2_push(t0, x.z, cx + 2); t2_push(t0, x.w, cx + 3);
        t2_push(t1, y.x, cy);     t2_push(t1, y.y, cy + 1);
        t2_push(t1, y.z, cy + 2); t2_push(t1, y.w, cy + 3);
    }
    t2_merge(t0, t1);
#pragma unroll
    for (int o = 16; o > 0; o >>= 1) {
        Top2 u = t2_shfl_xor(t0, o);
        t2_merge(t0, u);
    }
    if (lane == 0) g_m0[row] = t2_match(t0);
}

// ---------------------------------------------------------------------------
// Kernel 4: per-column top-2 partials. CTA = 256 cols x 512 rows.
//           Thread owns 4 columns (float4, coalesced); 4 row-subgroups
//           merged via smem. Writes NSPLIT partials per column.
//   grid: (M/256, N/512, B), block 256
// ---------------------------------------------------------------------------
__global__ void col_top2_part_kernel(const float* __restrict__ sim) {
    const int cg   = threadIdx.x & 63;   // col group: 4 cols
    const int rsub = threadIdx.x >> 6;   // 0..3
    const int m0 = blockIdx.x * 256;
    const int n0 = blockIdx.y * 512;
    const int b  = blockIdx.z;

    const float* base = sim + ((size_t)b * N + n0) * M + m0 + cg * 4;

    Top2 t[4];
#pragma unroll
    for (int j = 0; j < 4; ++j) t2_init(t[j]);

#pragma unroll 4
    for (int k = 0; k < 128; ++k) {
        int r = rsub + 4 * k;  // row within 512-slab
        float4 x = *reinterpret_cast<const float4*>(base + (size_t)r * M);
        int gn = n0 + r;
        t2_push(t[0], x.x, gn);
        t2_push(t[1], x.y, gn);
        t2_push(t[2], x.z, gn);
        t2_push(t[3], x.w, gn);
    }

    __shared__ Top2 sh[4][256];
#pragma unroll
    for (int j = 0; j < 4; ++j) sh[rsub][cg * 4 + j] = t[j];
    __syncthreads();

    // thread tid handles column tid: merge the 4 row-subgroup partials
    int c = threadIdx.x;
    Top2 r = sh[0][c];
    t2_merge(r, sh[1][c]);
    t2_merge(r, sh[2][c]);
    t2_merge(r, sh[3][c]);
    g_colpart[((size_t)(b * M + m0 + c)) * NSPLIT + blockIdx.y] = r;
}

// ---------------------------------------------------------------------------
// Kernel 5: merge column partials (8 contiguous Top2 = 128B per thread)
// ---------------------------------------------------------------------------
__global__ void col_merge_kernel() {
    int col = blockIdx.x * 256 + threadIdx.x;  // b*M + m
    const Top2* p = &g_colpart[(size_t)col * NSPLIT];
    Top2 t = p[0];
#pragma unroll
    for (int s = 1; s < NSPLIT; ++s) t2_merge(t, p[s]);
    g_m1[col] = t2_match(t);
}

// ---------------------------------------------------------------------------
// Kernel 6: mutual check + write matches/mscores
//   out layout: [matches0 | matches1 | mscores0 | mscores1 | sim]
// ---------------------------------------------------------------------------
__global__ void finalize_kernel(float* __restrict__ out) {
    int idx = blockIdx.x * 256 + threadIdx.x;  // b*N + n  (N == M)
    int b = idx / N, n = idx % N;

    int m0v = g_m0[idx];
    bool ok0 = (m0v > -1) && (g_m1[b * M + m0v] == n);
    out[idx]          = ok0 ? (float)m0v : -1.0f;
    out[2 * BN + idx] = ok0 ? 1.0f : 0.0f;

    int m1v = g_m1[idx];
    bool ok1 = (m1v > -1) && (g_m0[b * N + m1v] == n);
    out[BN + idx]     = ok1 ? (float)m1v : -1.0f;
    out[3 * BN + idx] = ok1 ? 1.0f : 0.0f;
}

// ---------------------------------------------------------------------------
// Launch
// ---------------------------------------------------------------------------
extern "C" void kernel_launch(void* const* d_in, const int* in_sizes, int n_in,
                              void* d_out, int out_size) {
    (void)in_sizes; (void)n_in; (void)out_size;
    const float* d0 = (const float*)d_in[0];
    const float* d1 = (const float*)d_in[1];
    float* out = (float*)d_out;
    float* sim = out + 4 * (size_t)BN;

    cudaFuncSetAttribute(sim_gemm_kernel,
                         cudaFuncAttributeMaxDynamicSharedMemorySize, SMEM_BYTES);

    norm_split_kernel<<<(B * N + B * M) / 8, 256>>>(d0, d1);
    sim_gemm_kernel<<<dim3(M / 128, N / 128, B), 256, SMEM_BYTES>>>(sim);
    row_top2_kernel<<<BN / 8, 256>>>(sim);
    col_top2_part_kernel<<<dim3(M / 256, N / 512, B), 256>>>(sim);
    col_merge_kernel<<<BN / 256, 256>>>();
    finalize_kernel<<<BN / 256, 256>>>(out);
}

// round 15
// speedup vs baseline: 2.6042x; 1.2731x over previous
#include <cuda_runtime.h>
#include <cuda_bf16.h>
#include <cstdint>
#include <cstddef>

// ---------------------------------------------------------------------------
// Problem constants
// ---------------------------------------------------------------------------
namespace {
constexpr int B = 8, N = 4096, M = 4096, D = 128;
constexpr int BN = B * N;  // 32768 (== B*M)
constexpr int NSPLIT = 16;  // row-splits for the column pass (N/256)
constexpr float RATIO2 = 0.64f;  // 0.8^2
constexpr float DIST2  = 0.49f;  // 0.7^2

// GEMM smem layout: 4 operand tiles of 128 rows x (128 bf16 + 8 pad) = 272B/row
constexpr int ROWB   = 272;                 // padded row bytes (17 * 16B)
constexpr int TILEB  = 128 * ROWB;          // 34816 B per operand tile
constexpr int SA_H = 0;
constexpr int SA_L = TILEB;
constexpr int SB_H = 2 * TILEB;
constexpr int SB_L = 3 * TILEB;
constexpr int SMEM_BYTES = 4 * TILEB;       // 139264
}  // namespace

// ---------------------------------------------------------------------------
// Device scratch (no allocations allowed)
// ---------------------------------------------------------------------------
__device__ __nv_bfloat16 g_ah[(size_t)B * N * D];
__device__ __nv_bfloat16 g_al[(size_t)B * N * D];
__device__ __nv_bfloat16 g_bh[(size_t)B * M * D];
__device__ __nv_bfloat16 g_bl[(size_t)B * M * D];

struct alignas(16) Top2 { float v1, v2; int i1, i2; };
__device__ Top2 g_colpart[(size_t)B * M * NSPLIT];  // [(b*M+m)][nsplit]
__device__ int  g_m0[B * N];
__device__ int  g_m1[B * M];

// ---------------------------------------------------------------------------
// PTX helpers (portable: sm_80+ instructions only, safe at target sm_103)
// ---------------------------------------------------------------------------
__device__ __forceinline__ uint32_t smem_u32(const void* p) {
    uint32_t a;
    asm("{ .reg .u64 t; cvta.to.shared.u64 t, %1; cvt.u32.u64 %0, t; }" : "=r"(a) : "l"(p));
    return a;
}

__device__ __forceinline__ void cp_async16(uint32_t saddr, const void* g) {
    asm volatile("cp.async.cg.shared.global [%0], [%1], 16;" :: "r"(saddr), "l"(g));
}
__device__ __forceinline__ void cp_commit() {
    asm volatile("cp.async.commit_group;");
}
template <int NLeft>
__device__ __forceinline__ void cp_wait() {
    asm volatile("cp.async.wait_group %0;" :: "n"(NLeft));
}

__device__ __forceinline__ void ldmatrix_x4(uint32_t (&r)[4], uint32_t addr) {
    asm volatile("ldmatrix.sync.aligned.m8n8.x4.shared.b16 {%0,%1,%2,%3}, [%4];"
                 : "=r"(r[0]), "=r"(r[1]), "=r"(r[2]), "=r"(r[3]) : "r"(addr));
}

__device__ __forceinline__ void mma_16816(float (&d)[4], const uint32_t (&a)[4],
                                          const uint32_t* b) {
    asm volatile(
        "mma.sync.aligned.m16n8k16.row.col.f32.bf16.bf16.f32 "
        "{%0,%1,%2,%3}, {%4,%5,%6,%7}, {%8,%9}, {%0,%1,%2,%3};"
        : "+f"(d[0]), "+f"(d[1]), "+f"(d[2]), "+f"(d[3])
        : "r"(a[0]), "r"(a[1]), "r"(a[2]), "r"(a[3]), "r"(b[0]), "r"(b[1]));
}

// ---------------------------------------------------------------------------
// Top-2 helpers (lax.top_k semantics: larger wins; tie -> lower index)
// ---------------------------------------------------------------------------
__device__ __forceinline__ void t2_init(Top2& t) {
    t.v1 = -2e30f; t.v2 = -2e30f; t.i1 = 0x7fffffff; t.i2 = 0x7fffffff;
}
// Full tie-aware push: used for merges (arbitrary index order).
__device__ __forceinline__ void t2_push(Top2& t, float v, int i) {
    if (v > t.v1 || (v == t.v1 && i < t.i1)) {
        t.v2 = t.v1; t.i2 = t.i1; t.v1 = v; t.i1 = i;
    } else if (v > t.v2 || (v == t.v2 && i < t.i2)) {
        t.v2 = v; t.i2 = i;
    }
}
// Branchless scan push: valid when indices are pushed in increasing order
// within the chain (a later equal value must NOT displace v1, and equals on
// v2 keep the earlier index). FMNMX chain latency 4 -> deep pipelining.
__device__ __forceinline__ void t2_scan_push(Top2& t, float v, int i) {
    float ov1 = t.v1;
    int   oi1 = t.i1;
    bool a = v > ov1;
    bool b = v > t.v2;
    t.v2 = fmaxf(fminf(v, ov1), t.v2);
    t.i2 = a ? oi1 : (b ? i : t.i2);
    t.v1 = a ? v : ov1;
    t.i1 = a ? i : oi1;
}
__device__ __forceinline__ void t2_merge(Top2& a, const Top2& b) {
    t2_push(a, b.v1, b.i1);
    t2_push(a, b.v2, b.i2);
}
__device__ __forceinline__ Top2 t2_shfl_xor(const Top2& t, int o) {
    Top2 u;
    u.v1 = __shfl_xor_sync(0xffffffffu, t.v1, o);
    u.v2 = __shfl_xor_sync(0xffffffffu, t.v2, o);
    u.i1 = __shfl_xor_sync(0xffffffffu, t.i1, o);
    u.i2 = __shfl_xor_sync(0xffffffffu, t.i2, o);
    return u;
}
__device__ __forceinline__ int t2_match(const Top2& t) {
    float d0 = 2.0f * (1.0f - t.v1);
    float d1 = 2.0f * (1.0f - t.v2);
    bool ok = (d0 <= RATIO2 * d1) && (d0 <= DIST2);
    return ok ? t.i1 : -1;
}

// ---------------------------------------------------------------------------
// Kernel 1: l2-normalize rows, split fp32 -> bf16 hi + bf16 lo
// ---------------------------------------------------------------------------
__global__ void norm_split_kernel(const float* __restrict__ d0, const float* __restrict__ d1) {
    int row  = blockIdx.x * 8 + (threadIdx.x >> 5);
    int lane = threadIdx.x & 31;

    const float* src;
    __nv_bfloat16 *ph, *pl;
    if (row < B * N) {
        src = d0 + (size_t)row * D;
        ph = g_ah + (size_t)row * D;
        pl = g_al + (size_t)row * D;
    } else {
        int r = row - B * N;
        src = d1 + (size_t)r * D;
        ph = g_bh + (size_t)r * D;
        pl = g_bl + (size_t)r * D;
    }
    float4 x = reinterpret_cast<const float4*>(src)[lane];
    float s = x.x * x.x + x.y * x.y + x.z * x.z + x.w * x.w;
#pragma unroll
    for (int o = 16; o > 0; o >>= 1) s += __shfl_xor_sync(0xffffffffu, s, o);
    float nrm = fmaxf(sqrtf(s), 1e-12f);

    float y[4] = {x.x / nrm, x.y / nrm, x.z / nrm, x.w / nrm};
#pragma unroll
    for (int i = 0; i < 4; ++i) {
        __nv_bfloat16 h = __float2bfloat16(y[i]);
        __nv_bfloat16 l = __float2bfloat16(y[i] - __bfloat162float(h));
        ph[lane * 4 + i] = h;
        pl[lane * 4 + i] = l;
    }
}

// ---------------------------------------------------------------------------
// Kernel 2: bf16 mma.sync GEMM  sim[b, r0:+128, c0:+128] = A @ B^T
//           split-bf16 (AhBh + AhBl + AlBh, fp32 accum).
//           cp.async 2-group pipeline: hi tiles (group A) feed pass 1 while
//           lo tiles (group B) are still in flight.
// ---------------------------------------------------------------------------
__global__ void __launch_bounds__(256, 1) sim_gemm_kernel(float* __restrict__ sim) {
    extern __shared__ char sm[];
    const int tid  = threadIdx.x;
    const int wid  = tid >> 5;
    const int lane = tid & 31;
    const int bz    = blockIdx.z;
    const int rbase = blockIdx.y * 128;  // d0 rows
    const int cbase = blockIdx.x * 128;  // d1 rows

    const uint32_t sb = smem_u32(sm);

    // ---- group A: hi tiles ----
    {
        const uint4* gAh = reinterpret_cast<const uint4*>(g_ah + ((size_t)bz * N + rbase) * D);
        const uint4* gBh = reinterpret_cast<const uint4*>(g_bh + ((size_t)bz * M + cbase) * D);
#pragma unroll
        for (int i = tid; i < 2048; i += 256) {
            int r = i >> 4, j = i & 15;
            uint32_t so = (uint32_t)r * ROWB + j * 16;
            cp_async16(sb + SA_H + so, gAh + i);
            cp_async16(sb + SB_H + so, gBh + i);
        }
    }
    cp_commit();
    // ---- group B: lo tiles ----
    {
        const uint4* gAl = reinterpret_cast<const uint4*>(g_al + ((size_t)bz * N + rbase) * D);
        const uint4* gBl = reinterpret_cast<const uint4*>(g_bl + ((size_t)bz * M + cbase) * D);
#pragma unroll
        for (int i = tid; i < 2048; i += 256) {
            int r = i >> 4, j = i & 15;
            uint32_t so = (uint32_t)r * ROWB + j * 16;
            cp_async16(sb + SA_L + so, gAl + i);
            cp_async16(sb + SB_L + so, gBl + i);
        }
    }
    cp_commit();

    const int wm = (wid & 3) * 32;   // warp row offset in tile
    const int wn = (wid >> 2) * 64;  // warp col offset in tile

    const int a_r  = ((lane >> 3) & 1) * 8 + (lane & 7);
    const int a_cb = ((lane >> 4) & 1) * 16;
    const int b_r  = ((lane >> 4) & 1) * 8 + (lane & 7);
    const int b_cb = ((lane >> 3) & 1) * 16;

    float acc[2][8][4];
#pragma unroll
    for (int mt = 0; mt < 2; ++mt)
#pragma unroll
        for (int nt = 0; nt < 8; ++nt)
#pragma unroll
            for (int q = 0; q < 4; ++q) acc[mt][nt][q] = 0.0f;

    auto compute_pass = [&](uint32_t Ab, uint32_t Bb) {
#pragma unroll
        for (int ks = 0; ks < 8; ++ks) {
            uint32_t a[2][4], b[4][4];
#pragma unroll
            for (int mt = 0; mt < 2; ++mt)
                ldmatrix_x4(a[mt], Ab + (uint32_t)(wm + mt * 16 + a_r) * ROWB + a_cb + ks * 32);
#pragma unroll
            for (int nt2 = 0; nt2 < 4; ++nt2)
                ldmatrix_x4(b[nt2], Bb + (uint32_t)(wn + nt2 * 16 + b_r) * ROWB + b_cb + ks * 32);
#pragma unroll
            for (int mt = 0; mt < 2; ++mt)
#pragma unroll
                for (int nt = 0; nt < 8; ++nt)
                    mma_16816(acc[mt][nt], a[mt], &b[nt >> 1][(nt & 1) * 2]);
        }
    };

    cp_wait<1>();          // hi tiles resident
    __syncthreads();
    compute_pass(sb + SA_H, sb + SB_H);   // AhBh (overlaps group-B copies)
    cp_wait<0>();          // lo tiles resident
    __syncthreads();
    compute_pass(sb + SA_H, sb + SB_L);   // AhBl
    compute_pass(sb + SA_L, sb + SB_H);   // AlBh

    // ---- epilogue: direct float2 stores ----
    const int rr = rbase + wm + (lane >> 2);
    const int cc = cbase + wn + (lane & 3) * 2;
#pragma unroll
    for (int mt = 0; mt < 2; ++mt)
#pragma unroll
        for (int nt = 0; nt < 8; ++nt) {
            float* p = sim + ((size_t)bz * N + rr + mt * 16) * M + cc + nt * 8;
            *reinterpret_cast<float2*>(p) = make_float2(acc[mt][nt][0], acc[mt][nt][1]);
            *reinterpret_cast<float2*>(p + 8 * (size_t)M) =
                make_float2(acc[mt][nt][2], acc[mt][nt][3]);
        }
}

// ---------------------------------------------------------------------------
// Kernel 3: per-row top-2 over M. One WARP per row, float4 loads,
//           4 independent branchless chains, shfl-xor merge.
// ---------------------------------------------------------------------------
__global__ void row_top2_kernel(const float* __restrict__ sim) {
    int row  = blockIdx.x * 8 + (threadIdx.x >> 5);  // b*N + n
    int lane = threadIdx.x & 31;
    const float4* p = reinterpret_cast<const float4*>(sim + (size_t)row * M);

    Top2 t[4];
#pragma unroll
    for (int q = 0; q < 4; ++q) t2_init(t[q]);

#pragma unroll 8
    for (int it = 0; it < 32; ++it) {  // 32 float4 per lane
        int j = lane + it * 32;
        float4 x = p[j];
        int c = j * 4;
        t2_scan_push(t[0], x.x, c);
        t2_scan_push(t[1], x.y, c + 1);
        t2_scan_push(t[2], x.z, c + 2);
        t2_scan_push(t[3], x.w, c + 3);
    }
    t2_merge(t[0], t[1]);
    t2_merge(t[2], t[3]);
    t2_merge(t[0], t[2]);
#pragma unroll
    for (int o = 16; o > 0; o >>= 1) {
        Top2 u = t2_shfl_xor(t[0], o);
        t2_merge(t[0], u);
    }
    if (lane == 0) g_m0[row] = t2_match(t[0]);
}

// ---------------------------------------------------------------------------
// Kernel 4: per-column top-2 partials. CTA = 256 cols x 256 rows.
//           Thread owns 4 columns (float4, coalesced), branchless chains;
//           4 row-subgroups merged via smem. grid (M/256, N/256, B).
// ---------------------------------------------------------------------------
__global__ void col_top2_part_kernel(const float* __restrict__ sim) {
    const int cg   = threadIdx.x & 63;   // col group: 4 cols
    const int rsub = threadIdx.x >> 6;   // 0..3
    const int m0 = blockIdx.x * 256;
    const int n0 = blockIdx.y * 256;
    const int b  = blockIdx.z;

    const float* base = sim + ((size_t)b * N + n0 + rsub) * M + m0 + cg * 4;

    Top2 t[4];
#pragma unroll
    for (int j = 0; j < 4; ++j) t2_init(t[j]);

#pragma unroll 8
    for (int k = 0; k < 64; ++k) {
        float4 x = *reinterpret_cast<const float4*>(base + (size_t)(4 * k) * M);
        int gn = n0 + rsub + 4 * k;
        t2_scan_push(t[0], x.x, gn);
        t2_scan_push(t[1], x.y, gn);
        t2_scan_push(t[2], x.z, gn);
        t2_scan_push(t[3], x.w, gn);
    }

    __shared__ Top2 sh[4][256];
#pragma unroll
    for (int j = 0; j < 4; ++j) sh[rsub][cg * 4 + j] = t[j];
    __syncthreads();

    int c = threadIdx.x;
    Top2 r = sh[0][c];
    t2_merge(r, sh[1][c]);
    t2_merge(r, sh[2][c]);
    t2_merge(r, sh[3][c]);
    g_colpart[((size_t)(b * M + m0 + c)) * NSPLIT + blockIdx.y] = r;
}

// ---------------------------------------------------------------------------
// Kernel 5: merge column partials (16 contiguous Top2 = 256B per thread)
// ---------------------------------------------------------------------------
__global__ void col_merge_kernel() {
    int col = blockIdx.x * 256 + threadIdx.x;  // b*M + m
    const Top2* p = &g_colpart[(size_t)col * NSPLIT];
    Top2 t = p[0];
#pragma unroll
    for (int s = 1; s < NSPLIT; ++s) t2_merge(t, p[s]);
    g_m1[col] = t2_match(t);
}

// ---------------------------------------------------------------------------
// Kernel 6: mutual check + write matches/mscores
//   out layout: [matches0 | matches1 | mscores0 | mscores1 | sim]
// ---------------------------------------------------------------------------
__global__ void finalize_kernel(float* __restrict__ out) {
    int idx = blockIdx.x * 256 + threadIdx.x;  // b*N + n  (N == M)
    int b = idx / N, n = idx % N;

    int m0v = g_m0[idx];
    bool ok0 = (m0v > -1) && (g_m1[b * M + m0v] == n);
    out[idx]          = ok0 ? (float)m0v : -1.0f;
    out[2 * BN + idx] = ok0 ? 1.0f : 0.0f;

    int m1v = g_m1[idx];
    bool ok1 = (m1v > -1) && (g_m0[b * N + m1v] == n);
    out[BN + idx]     = ok1 ? (float)m1v : -1.0f;
    out[3 * BN + idx] = ok1 ? 1.0f : 0.0f;
}

// ---------------------------------------------------------------------------
// Launch
// ---------------------------------------------------------------------------
extern "C" void kernel_launch(void* const* d_in, const int* in_sizes, int n_in,
                              void* d_out, int out_size) {
    (void)in_sizes; (void)n_in; (void)out_size;
    const float* d0 = (const float*)d_in[0];
    const float* d1 = (const float*)d_in[1];
    float* out = (float*)d_out;
    float* sim = out + 4 * (size_t)BN;

    cudaFuncSetAttribute(sim_gemm_kernel,
                         cudaFuncAttributeMaxDynamicSharedMemorySize, SMEM_BYTES);

    norm_split_kernel<<<(B * N + B * M) / 8, 256>>>(d0, d1);
    sim_gemm_kernel<<<dim3(M / 128, N / 128, B), 256, SMEM_BYTES>>>(sim);
    row_top2_kernel<<<BN / 8, 256>>>(sim);
    col_top2_part_kernel<<<dim3(M / 256, N / 256, B), 256>>>(sim);
    col_merge_kernel<<<BN / 256, 256>>>();
    finalize_kernel<<<BN / 256, 256>>>(out);
}